// round 1
// baseline (speedup 1.0000x reference)
#include <cuda_runtime.h>
#include <cuda_bf16.h>

#define N_NODE 100000
#define NEDGE  1600000
#define HID    128
#define OUTD   64

typedef unsigned long long ull;

// ---------------- scratch (device globals: allocation-free) ----------------
__device__ float d_agg_wu[N_NODE * 4];
__device__ float d_deg_wu[N_NODE];
__device__ float d_agg_uu[N_NODE * 16];
__device__ float d_deg_uu[N_NODE];
__device__ float d_h[N_NODE * HID];     // h_user pre-BN
__device__ float d_xp[N_NODE * HID];    // GAT projected features
__device__ float d_als[N_NODE * 4];
__device__ float d_ald[N_NODE * 4];
__device__ float d_ssum[N_NODE * 4];    // segment softmax denominators
__device__ float d_gat[N_NODE * HID];   // GAT output accumulators
__device__ float d_stats[1024];
// stats layout: [0:128) sum1 [128:256) sq1 [256:384) sum2 [384:512) sq2
//               [512:640) scale1 [640:768) shift1 [768:896) scale2 [896:1024) shift2

// ---------------- f32x2 packed helpers ----------------
__device__ __forceinline__ ull ffma2(ull a, ull b, ull c) {
    ull d;
    asm("fma.rn.f32x2 %0, %1, %2, %3;" : "=l"(d) : "l"(a), "l"(b), "l"(c));
    return d;
}
__device__ __forceinline__ ull pack2f(float x, float y) {
    ull r; asm("mov.b64 %0, {%1, %2};" : "=l"(r) : "f"(x), "f"(y)); return r;
}
__device__ __forceinline__ float sum2f(ull v) {
    float a, b; asm("mov.b64 {%0, %1}, %2;" : "=f"(a), "=f"(b) : "l"(v));
    return a + b;
}

// ---------------- kernels ----------------
__global__ void k_zero() {
    int i = blockIdx.x * blockDim.x + threadIdx.x;
    int st = gridDim.x * blockDim.x;
    for (int j = i; j < N_NODE * HID; j += st) d_gat[j] = 0.f;
    for (int j = i; j < N_NODE * 16; j += st) d_agg_uu[j] = 0.f;
    for (int j = i; j < N_NODE * 4; j += st) { d_agg_wu[j] = 0.f; d_ssum[j] = 0.f; }
    for (int j = i; j < N_NODE; j += st) { d_deg_wu[j] = 0.f; d_deg_uu[j] = 0.f; }
    for (int j = i; j < 512; j += st) d_stats[j] = 0.f;
}

// wallet->user edge scatter: aggregate raw 4-dim wallet features per dst user
__global__ void k_edge_wu(const float* __restrict__ xw, const int* __restrict__ ei) {
    int e = blockIdx.x * blockDim.x + threadIdx.x;
    int st = gridDim.x * blockDim.x;
    for (; e < NEDGE; e += st) {
        int s = __ldg(&ei[e]);
        int d = __ldg(&ei[NEDGE + e]);
        float4 v = __ldg(((const float4*)xw) + s);
        float* a = &d_agg_wu[d * 4];
        atomicAdd(a + 0, v.x); atomicAdd(a + 1, v.y);
        atomicAdd(a + 2, v.z); atomicAdd(a + 3, v.w);
        atomicAdd(&d_deg_wu[d], 1.0f);
    }
}

// user->user edge scatter: 4 threads/edge, 4 floats each
__global__ void k_edge_uu(const float* __restrict__ xu, const int* __restrict__ ei) {
    int idx = blockIdx.x * blockDim.x + threadIdx.x;
    int st = gridDim.x * blockDim.x;
    for (; idx < NEDGE * 4; idx += st) {
        int e = idx >> 2, q = idx & 3;
        int s = __ldg(&ei[e]);
        int d = __ldg(&ei[NEDGE + e]);
        float4 v = __ldg(((const float4*)xu) + s * 4 + q);
        float* a = &d_agg_uu[d * 16 + q * 4];
        atomicAdd(a + 0, v.x); atomicAdd(a + 1, v.y);
        atomicAdd(a + 2, v.z); atomicAdd(a + 3, v.w);
        if (q == 0) atomicAdd(&d_deg_uu[d], 1.0f);
    }
}

// per-node SAGE linear layers + relu + sum, with BN1 stat accumulation
__global__ void __launch_bounds__(128) k_sage_node(
    const float* __restrict__ xu,
    const float* __restrict__ wl1, const float* __restrict__ b1, const float* __restrict__ wr1,
    const float* __restrict__ wl2, const float* __restrict__ b2, const float* __restrict__ wr2)
{
    __shared__ float s_wl1[4 * 128];
    __shared__ float s_wr1[16 * 128];
    __shared__ float s_wl2[16 * 128];
    __shared__ float s_wr2[16 * 128];
    __shared__ float s_b1[128], s_b2[128];
    __shared__ float s_in[36]; // [0:4) agg_wu/deg, [4:20) x_user, [20:36) agg_uu/deg
    int c = threadIdx.x;
    for (int i = c; i < 4 * 128; i += 128) s_wl1[i] = wl1[i];
    for (int i = c; i < 16 * 128; i += 128) {
        s_wr1[i] = wr1[i]; s_wl2[i] = wl2[i]; s_wr2[i] = wr2[i];
    }
    s_b1[c] = b1[c]; s_b2[c] = b2[c];
    __syncthreads();

    float lsum = 0.f, lsq = 0.f;
    for (int i = blockIdx.x; i < N_NODE; i += gridDim.x) {
        if (c < 4) {
            float inv = 1.f / fmaxf(d_deg_wu[i], 1.f);
            s_in[c] = d_agg_wu[i * 4 + c] * inv;
        } else if (c < 20) {
            s_in[c] = xu[i * 16 + (c - 4)];
        } else if (c < 36) {
            float inv = 1.f / fmaxf(d_deg_uu[i], 1.f);
            s_in[c] = d_agg_uu[i * 16 + (c - 20)] * inv;
        }
        __syncthreads();
        float a1 = s_b1[c];
        #pragma unroll
        for (int k = 0; k < 4; k++)  a1 = fmaf(s_in[k],      s_wl1[k * 128 + c], a1);
        #pragma unroll
        for (int k = 0; k < 16; k++) a1 = fmaf(s_in[4 + k],  s_wr1[k * 128 + c], a1);
        a1 = fmaxf(a1, 0.f);
        float a2 = s_b2[c];
        #pragma unroll
        for (int k = 0; k < 16; k++) a2 = fmaf(s_in[20 + k], s_wl2[k * 128 + c], a2);
        #pragma unroll
        for (int k = 0; k < 16; k++) a2 = fmaf(s_in[4 + k],  s_wr2[k * 128 + c], a2);
        a2 = fmaxf(a2, 0.f);
        float h = a1 + a2;
        d_h[i * HID + c] = h;
        lsum += h;
        lsq = fmaf(h, h, lsq);
        __syncthreads();
    }
    atomicAdd(&d_stats[c], lsum);
    atomicAdd(&d_stats[128 + c], lsq);
}

__global__ void k_bn_fin(const float* __restrict__ g, const float* __restrict__ b,
                         int sIn, int sOut) {
    int c = threadIdx.x;
    float invN = 1.0f / (float)N_NODE;
    float mean = d_stats[sIn + c] * invN;
    float var = d_stats[sIn + 128 + c] * invN - mean * mean;
    float sc = g[c] * rsqrtf(var + 1e-5f);
    d_stats[sOut + c] = sc;
    d_stats[sOut + 128 + c] = fmaf(-mean, sc, b[c]);
}

// xp = BN1(h) @ gat_w; also per-head attention logit halves al_s, al_d.
// register-tiled f32x2 GEMM: 256 thr, thread owns 2 channels x 32 k (packed pairs).
__global__ void __launch_bounds__(256) k_xp(
    const float* __restrict__ W, const float* __restrict__ a_src, const float* __restrict__ a_dst)
{
    __shared__ __align__(16) float sh[2][128];
    __shared__ float red[2][512];
    int t = threadIdx.x;
    int kq = t >> 6;          // 0..3 -> k slice [kq*32, kq*32+32)
    int k0 = kq * 32;
    int cp = t & 63;
    int ch0 = cp * 2, ch1 = ch0 + 1;

    ull w0[16], w1[16];
    #pragma unroll
    for (int j = 0; j < 16; j++) {
        int ka = k0 + 2 * j, kb = ka + 1;
        w0[j] = pack2f(__ldg(&W[ka * 128 + ch0]), __ldg(&W[kb * 128 + ch0]));
        w1[j] = pack2f(__ldg(&W[ka * 128 + ch1]), __ldg(&W[kb * 128 + ch1]));
    }
    int sc_c = t & 127;
    int sn = t >> 7;
    float scale = d_stats[512 + sc_c];
    float shift = d_stats[640 + sc_c];
    float asr = __ldg(&a_src[sc_c]);
    float adr = __ldg(&a_dst[sc_c]);

    for (int i0 = blockIdx.x * 2; i0 < N_NODE; i0 += gridDim.x * 2) {
        sh[sn][sc_c] = fmaf(d_h[(i0 + sn) * HID + sc_c], scale, shift);
        __syncthreads();
        ull acc00 = 0ull, acc01 = 0ull, acc10 = 0ull, acc11 = 0ull;
        #pragma unroll
        for (int j = 0; j < 16; j++) {
            ull h0 = *(const ull*)&sh[0][k0 + 2 * j];
            ull h1 = *(const ull*)&sh[1][k0 + 2 * j];
            acc00 = ffma2(h0, w0[j], acc00);
            acc01 = ffma2(h0, w1[j], acc01);
            acc10 = ffma2(h1, w0[j], acc10);
            acc11 = ffma2(h1, w1[j], acc11);
        }
        red[0][kq * 128 + ch0] = sum2f(acc00);
        red[0][kq * 128 + ch1] = sum2f(acc01);
        red[1][kq * 128 + ch0] = sum2f(acc10);
        red[1][kq * 128 + ch1] = sum2f(acc11);
        __syncthreads();
        {
            int c = sc_c;
            float xpv = red[sn][c] + red[sn][128 + c] + red[sn][256 + c] + red[sn][384 + c];
            int ii = i0 + sn;
            d_xp[ii * HID + c] = xpv;
            float vs = xpv * asr, vd = xpv * adr;
            #pragma unroll
            for (int o = 16; o > 0; o >>= 1) {
                vs += __shfl_xor_sync(0xffffffffu, vs, o);
                vd += __shfl_xor_sync(0xffffffffu, vd, o);
            }
            if ((c & 31) == 0) {
                d_als[ii * 4 + (c >> 5)] = vs;
                d_ald[ii * 4 + (c >> 5)] = vd;
            }
        }
        __syncthreads();
    }
}

// softmax denominators (no max-shift needed: logits bounded). Includes self-loops.
__global__ void k_gat_sum(const int* __restrict__ ei) {
    int idx = blockIdx.x * blockDim.x + threadIdx.x;
    int st = gridDim.x * blockDim.x;
    for (; idx < NEDGE + N_NODE; idx += st) {
        int s, d;
        if (idx < NEDGE) { s = __ldg(&ei[idx]); d = __ldg(&ei[NEDGE + idx]); }
        else             { s = d = idx - NEDGE; }
        float4 as = __ldg((const float4*)&d_als[s * 4]);
        float4 ad = __ldg((const float4*)&d_ald[d * 4]);
        float l0 = as.x + ad.x; l0 = l0 > 0.f ? l0 : 0.2f * l0;
        float l1 = as.y + ad.y; l1 = l1 > 0.f ? l1 : 0.2f * l1;
        float l2 = as.z + ad.z; l2 = l2 > 0.f ? l2 : 0.2f * l2;
        float l3 = as.w + ad.w; l3 = l3 > 0.f ? l3 : 0.2f * l3;
        float* ssp = &d_ssum[d * 4];
        atomicAdd(ssp + 0, expf(l0));
        atomicAdd(ssp + 1, expf(l1));
        atomicAdd(ssp + 2, expf(l2));
        atomicAdd(ssp + 3, expf(l3));
    }
}

// weighted aggregation: warp per edge, 4 channels per lane
__global__ void k_gat_agg(const int* __restrict__ ei) {
    int lane = threadIdx.x & 31;
    int warpId = (blockIdx.x * blockDim.x + threadIdx.x) >> 5;
    int nWarps = (gridDim.x * blockDim.x) >> 5;
    int c = lane * 4;
    int h = lane >> 3;
    for (int idx = warpId; idx < NEDGE + N_NODE; idx += nWarps) {
        int s, d;
        if (idx < NEDGE) { s = __ldg(&ei[idx]); d = __ldg(&ei[NEDGE + idx]); }
        else             { s = d = idx - NEDGE; }
        float l = __ldg(&d_als[s * 4 + h]) + __ldg(&d_ald[d * 4 + h]);
        l = l > 0.f ? l : 0.2f * l;
        float alpha = expf(l) / (__ldg(&d_ssum[d * 4 + h]) + 1e-16f);
        float4 xv = __ldg((const float4*)&d_xp[s * HID + c]);
        float* outp = &d_gat[d * HID + c];
        atomicAdd(outp + 0, xv.x * alpha);
        atomicAdd(outp + 1, xv.y * alpha);
        atomicAdd(outp + 2, xv.z * alpha);
        atomicAdd(outp + 3, xv.w * alpha);
    }
}

// bias + relu + BN2 stats (in place on d_gat)
__global__ void __launch_bounds__(128) k_post(const float* __restrict__ gat_b) {
    int c = threadIdx.x;
    float bias = __ldg(&gat_b[c]);
    float lsum = 0.f, lsq = 0.f;
    for (int i = blockIdx.x; i < N_NODE; i += gridDim.x) {
        float g = d_gat[i * HID + c] + bias;
        g = fmaxf(g, 0.f);
        d_gat[i * HID + c] = g;
        lsum += g;
        lsq = fmaf(g, g, lsq);
    }
    atomicAdd(&d_stats[256 + c], lsum);
    atomicAdd(&d_stats[384 + c], lsq);
}

// out = relu(BN2(g) @ proj_w + proj_b); register-tiled f32x2
__global__ void __launch_bounds__(256) k_proj(
    const float* __restrict__ PW, const float* __restrict__ pb, float* __restrict__ out)
{
    __shared__ __align__(16) float sh[2][128];
    __shared__ float red[2][8 * 64];
    int t = threadIdx.x;
    int kq = t >> 5;          // 0..7 -> k slice of 16
    int k0 = kq * 16;
    int cp = t & 31;
    int ch0 = cp * 2, ch1 = ch0 + 1;

    ull w0[8], w1[8];
    #pragma unroll
    for (int j = 0; j < 8; j++) {
        int ka = k0 + 2 * j, kb = ka + 1;
        w0[j] = pack2f(__ldg(&PW[ka * 64 + ch0]), __ldg(&PW[kb * 64 + ch0]));
        w1[j] = pack2f(__ldg(&PW[ka * 64 + ch1]), __ldg(&PW[kb * 64 + ch1]));
    }
    int sc_c = t & 127;
    int sn = t >> 7;
    float scale = d_stats[768 + sc_c];
    float shift = d_stats[896 + sc_c];

    for (int i0 = blockIdx.x * 2; i0 < N_NODE; i0 += gridDim.x * 2) {
        sh[sn][sc_c] = fmaf(d_gat[(i0 + sn) * HID + sc_c], scale, shift);
        __syncthreads();
        ull acc00 = 0ull, acc01 = 0ull, acc10 = 0ull, acc11 = 0ull;
        #pragma unroll
        for (int j = 0; j < 8; j++) {
            ull h0 = *(const ull*)&sh[0][k0 + 2 * j];
            ull h1 = *(const ull*)&sh[1][k0 + 2 * j];
            acc00 = ffma2(h0, w0[j], acc00);
            acc01 = ffma2(h0, w1[j], acc01);
            acc10 = ffma2(h1, w0[j], acc10);
            acc11 = ffma2(h1, w1[j], acc11);
        }
        red[0][kq * 64 + ch0] = sum2f(acc00);
        red[0][kq * 64 + ch1] = sum2f(acc01);
        red[1][kq * 64 + ch0] = sum2f(acc10);
        red[1][kq * 64 + ch1] = sum2f(acc11);
        __syncthreads();
        if (t < 128) {
            int n = t >> 6, o = t & 63;
            float v = 0.f;
            #pragma unroll
            for (int q = 0; q < 8; q++) v += red[n][q * 64 + o];
            v += __ldg(&pb[o]);
            out[(i0 + n) * OUTD + o] = fmaxf(v, 0.f);
        }
        __syncthreads();
    }
}

// ---------------- launch ----------------
extern "C" void kernel_launch(void* const* d_in, const int* in_sizes, int n_in,
                              void* d_out, int out_size) {
    const float* x_user   = (const float*)d_in[0];
    const float* x_wallet = (const float*)d_in[1];
    // d_in[2..4]: u2w SAGE (dead code — never reaches output)
    const float* w_w2u_l = (const float*)d_in[5];
    const float* b_w2u   = (const float*)d_in[6];
    const float* w_w2u_r = (const float*)d_in[7];
    const float* w_u2u_l = (const float*)d_in[8];
    const float* b_u2u   = (const float*)d_in[9];
    const float* w_u2u_r = (const float*)d_in[10];
    const float* bn_u_g  = (const float*)d_in[11];
    const float* bn_u_b  = (const float*)d_in[12];
    // d_in[13..14]: bn_w (dead)
    const float* gat_w  = (const float*)d_in[15];
    const float* gat_as = (const float*)d_in[16];
    const float* gat_ad = (const float*)d_in[17];
    const float* gat_b  = (const float*)d_in[18];
    const float* bn2_g  = (const float*)d_in[19];
    const float* bn2_b  = (const float*)d_in[20];
    const float* proj_w = (const float*)d_in[21];
    const float* proj_b = (const float*)d_in[22];
    // d_in[23]: ei_uw (dead)
    const int* ei_wu = (const int*)d_in[24];
    const int* ei_uu = (const int*)d_in[25];
    float* out = (float*)d_out;

    k_zero<<<4096, 256>>>();
    k_edge_wu<<<6250, 256>>>(x_wallet, ei_wu);
    k_edge_uu<<<25000, 256>>>(x_user, ei_uu);
    k_sage_node<<<1184, 128>>>(x_user, w_w2u_l, b_w2u, w_w2u_r, w_u2u_l, b_u2u, w_u2u_r);
    k_bn_fin<<<1, 128>>>(bn_u_g, bn_u_b, 0, 512);
    k_xp<<<1024, 256>>>(gat_w, gat_as, gat_ad);
    k_gat_sum<<<6641, 256>>>(ei_uu);
    k_gat_agg<<<8192, 256>>>(ei_uu);
    k_post<<<2048, 128>>>(gat_b);
    k_bn_fin<<<1, 128>>>(bn2_g, bn2_b, 256, 768);
    k_proj<<<1024, 256>>>(proj_w, proj_b, out);
}

// round 3
// speedup vs baseline: 2.0308x; 2.0308x over previous
#include <cuda_runtime.h>
#include <cuda_bf16.h>

#define N_NODE 100000
#define NEDGE  1600000
#define HID    128
#define OUTD   64

typedef unsigned long long ull;

// ---------------- scratch (device globals: allocation-free) ----------------
__device__ float d_agg_wu[N_NODE * 4];
__device__ float d_deg_wu[N_NODE];
__device__ float d_agg_uu[N_NODE * 16];   // stores MEAN directly
__device__ float d_h[N_NODE * HID];       // h_user pre-BN
__device__ float d_xp[N_NODE * HID];      // GAT projected features
__device__ float d_als[N_NODE * 4];
__device__ float d_ald[N_NODE * 4];
__device__ float d_gat[N_NODE * HID];     // GAT output (post bias+relu)
__device__ float d_stats[1024];
// stats: [0:128) sum1 [128:256) sq1 [256:384) sum2 [384:512) sq2
//        [512:640) scale1 [640:768) shift1 [768:896) scale2 [896:1024) shift2

// CSR for ei_uu grouped by dst
__device__ int d_cnt[N_NODE];
__device__ int d_rowptr[N_NODE + 2];
__device__ int d_cur[N_NODE];
__device__ int d_ssrc[NEDGE];
__device__ int d_part[128];

// ---------------- f32x2 packed helpers ----------------
__device__ __forceinline__ ull ffma2(ull a, ull b, ull c) {
    ull d;
    asm("fma.rn.f32x2 %0, %1, %2, %3;" : "=l"(d) : "l"(a), "l"(b), "l"(c));
    return d;
}
__device__ __forceinline__ ull pack2f(float x, float y) {
    ull r; asm("mov.b64 %0, {%1, %2};" : "=l"(r) : "f"(x), "f"(y)); return r;
}
__device__ __forceinline__ float sum2f(ull v) {
    float a, b; asm("mov.b64 {%0, %1}, %2;" : "=f"(a), "=f"(b) : "l"(v));
    return a + b;
}
__device__ __forceinline__ void red_add_v4(float* p, float4 v) {
    asm volatile("red.global.add.v4.f32 [%0], {%1,%2,%3,%4};"
                 :: "l"(p), "f"(v.x), "f"(v.y), "f"(v.z), "f"(v.w) : "memory");
}

// ---------------- init ----------------
__global__ void k_zero() {
    int i = blockIdx.x * blockDim.x + threadIdx.x;
    int st = gridDim.x * blockDim.x;
    for (int j = i; j < N_NODE; j += st) { d_cnt[j] = 0; d_deg_wu[j] = 0.f; }
    for (int j = i; j < N_NODE * 4; j += st) d_agg_wu[j] = 0.f;
    for (int j = i; j < 512; j += st) d_stats[j] = 0.f;
}

// ---------------- CSR build for ei_uu (grouped by dst) ----------------
__global__ void k_hist(const int* __restrict__ ei) {
    int e = blockIdx.x * blockDim.x + threadIdx.x;
    int st = gridDim.x * blockDim.x;
    for (; e < NEDGE; e += st) atomicAdd(&d_cnt[__ldg(&ei[NEDGE + e])], 1);
}

__global__ void k_scan1() { // 98 blocks x 256
    int b = blockIdx.x, t = threadIdx.x;
    int base = b * 1024 + t * 4;
    int s = 0;
    #pragma unroll
    for (int k = 0; k < 4; k++) { int i = base + k; if (i < N_NODE) s += d_cnt[i]; }
    __shared__ int sh[256];
    sh[t] = s; __syncthreads();
    for (int o = 128; o; o >>= 1) { if (t < o) sh[t] += sh[t + o]; __syncthreads(); }
    if (t == 0) d_part[b] = sh[0];
}

__global__ void k_scan2() { // 1 block x 128
    int t = threadIdx.x;
    __shared__ int sp[98];
    if (t < 98) sp[t] = d_part[t];
    __syncthreads();
    if (t == 0) {
        int run = 0;
        for (int b = 0; b < 98; b++) { int v = sp[b]; sp[b] = run; run += v; }
    }
    __syncthreads();
    if (t < 98) d_part[t] = sp[t];
}

__global__ void k_scan3() { // 98 blocks x 256
    int b = blockIdx.x, t = threadIdx.x;
    int base = b * 1024 + t * 4;
    int v[4];
    #pragma unroll
    for (int k = 0; k < 4; k++) { int i = base + k; v[k] = (i < N_NODE) ? d_cnt[i] : 0; }
    int tot = v[0] + v[1] + v[2] + v[3];
    __shared__ int sh[256];
    sh[t] = tot; __syncthreads();
    for (int o = 1; o < 256; o <<= 1) {
        int x = (t >= o) ? sh[t - o] : 0;
        __syncthreads();
        sh[t] += x;
        __syncthreads();
    }
    int baseOff = d_part[b] + sh[t] - tot;
    int pref = 0;
    #pragma unroll
    for (int k = 0; k < 4; k++) {
        int i = base + k;
        if (i <= N_NODE) {
            d_rowptr[i] = baseOff + pref;
            if (i < N_NODE) d_cur[i] = baseOff + pref;
        }
        pref += v[k];
    }
}

__global__ void k_scatter(const int* __restrict__ ei) {
    int e = blockIdx.x * blockDim.x + threadIdx.x;
    int st = gridDim.x * blockDim.x;
    for (; e < NEDGE; e += st) {
        int s = __ldg(&ei[e]);
        int d = __ldg(&ei[NEDGE + e]);
        int p = atomicAdd(&d_cur[d], 1);
        d_ssrc[p] = s;
    }
}

// wallet->user edge scatter: vector RED of raw 4-dim wallet features
__global__ void k_edge_wu(const float* __restrict__ xw, const int* __restrict__ ei) {
    int e = blockIdx.x * blockDim.x + threadIdx.x;
    int st = gridDim.x * blockDim.x;
    for (; e < NEDGE; e += st) {
        int s = __ldg(&ei[e]);
        int d = __ldg(&ei[NEDGE + e]);
        float4 v = __ldg(((const float4*)xw) + s);
        red_add_v4(&d_agg_wu[d * 4], v);
        atomicAdd(&d_deg_wu[d], 1.0f);
    }
}

// SAGE u2u mean aggregation via CSR: warp per dst, no atomics, stores MEAN
__global__ void __launch_bounds__(256) k_agg_uu(const float* __restrict__ xu) {
    int t = threadIdx.x, lane = t & 31;
    int warpId = (blockIdx.x * blockDim.x + t) >> 5;
    int nW = (gridDim.x * blockDim.x) >> 5;
    int half = lane >> 4, ch = lane & 15;
    for (int d = warpId; d < N_NODE; d += nW) {
        int start = d_rowptr[d], end = d_rowptr[d + 1];
        float acc = 0.f;
        for (int e = start + half; e < end; e += 2) {
            int s = __ldg(&d_ssrc[e]);
            acc += __ldg(&xu[s * 16 + ch]);
        }
        acc += __shfl_xor_sync(0xffffffffu, acc, 16);
        if (lane < 16) {
            float inv = 1.f / fmaxf((float)(end - start), 1.f);
            d_agg_uu[d * 16 + ch] = acc * inv;
        }
    }
}

// SAGE node phase: weights in registers, 2 nodes per iteration (4 FMA chains)
__global__ void __launch_bounds__(128) k_sage_node(
    const float* __restrict__ xu,
    const float* __restrict__ wl1, const float* __restrict__ b1, const float* __restrict__ wr1,
    const float* __restrict__ wl2, const float* __restrict__ b2, const float* __restrict__ wr2)
{
    int c = threadIdx.x;
    float rwl1[4], rwr1[16], rwl2[16], rwr2[16];
    #pragma unroll
    for (int k = 0; k < 4; k++) rwl1[k] = __ldg(&wl1[k * 128 + c]);
    #pragma unroll
    for (int k = 0; k < 16; k++) {
        rwr1[k] = __ldg(&wr1[k * 128 + c]);
        rwl2[k] = __ldg(&wl2[k * 128 + c]);
        rwr2[k] = __ldg(&wr2[k * 128 + c]);
    }
    float rb1 = __ldg(&b1[c]), rb2 = __ldg(&b2[c]);
    __shared__ float s_in[2][36]; // [0:4) mean_wu, [4:20) xu, [20:36) mean_uu
    float lsum = 0.f, lsq = 0.f;
    for (int i0 = blockIdx.x * 2; i0 < N_NODE; i0 += gridDim.x * 2) {
        if (c < 72) {
            int n = c >= 36, j = c - n * 36;
            int i = i0 + n;
            float v;
            if (j < 4)       v = d_agg_wu[i * 4 + j] / fmaxf(d_deg_wu[i], 1.f);
            else if (j < 20) v = __ldg(&xu[i * 16 + j - 4]);
            else             v = d_agg_uu[i * 16 + j - 20];
            s_in[n][j] = v;
        }
        __syncthreads();
        float a10 = rb1, a11 = rb1, a20 = rb2, a21 = rb2;
        #pragma unroll
        for (int k = 0; k < 4; k++) {
            a10 = fmaf(s_in[0][k], rwl1[k], a10);
            a11 = fmaf(s_in[1][k], rwl1[k], a11);
        }
        #pragma unroll
        for (int k = 0; k < 16; k++) {
            float x0 = s_in[0][4 + k], x1 = s_in[1][4 + k];
            a10 = fmaf(x0, rwr1[k], a10);
            a11 = fmaf(x1, rwr1[k], a11);
            a20 = fmaf(x0, rwr2[k], a20);
            a21 = fmaf(x1, rwr2[k], a21);
            float g0 = s_in[0][20 + k], g1 = s_in[1][20 + k];
            a20 = fmaf(g0, rwl2[k], a20);
            a21 = fmaf(g1, rwl2[k], a21);
        }
        float h0 = fmaxf(a10, 0.f) + fmaxf(a20, 0.f);
        float h1 = fmaxf(a11, 0.f) + fmaxf(a21, 0.f);
        d_h[i0 * HID + c] = h0;
        d_h[(i0 + 1) * HID + c] = h1;
        lsum += h0 + h1;
        lsq = fmaf(h0, h0, lsq);
        lsq = fmaf(h1, h1, lsq);
        __syncthreads();
    }
    atomicAdd(&d_stats[c], lsum);
    atomicAdd(&d_stats[128 + c], lsq);
}

__global__ void k_bn_fin(const float* __restrict__ g, const float* __restrict__ b,
                         int sIn, int sOut) {
    int c = threadIdx.x;
    float invN = 1.0f / (float)N_NODE;
    float mean = d_stats[sIn + c] * invN;
    float var = d_stats[sIn + 128 + c] * invN - mean * mean;
    float sc = g[c] * rsqrtf(var + 1e-5f);
    d_stats[sOut + c] = sc;
    d_stats[sOut + 128 + c] = fmaf(-mean, sc, b[c]);
}

// xp = BN1(h) @ gat_w; also per-head attention logit halves al_s, al_d.
__global__ void __launch_bounds__(256) k_xp(
    const float* __restrict__ W, const float* __restrict__ a_src, const float* __restrict__ a_dst)
{
    __shared__ __align__(16) float sh[2][128];
    __shared__ float red[2][512];
    int t = threadIdx.x;
    int kq = t >> 6;
    int k0 = kq * 32;
    int cp = t & 63;
    int ch0 = cp * 2, ch1 = ch0 + 1;

    ull w0[16], w1[16];
    #pragma unroll
    for (int j = 0; j < 16; j++) {
        int ka = k0 + 2 * j, kb = ka + 1;
        w0[j] = pack2f(__ldg(&W[ka * 128 + ch0]), __ldg(&W[kb * 128 + ch0]));
        w1[j] = pack2f(__ldg(&W[ka * 128 + ch1]), __ldg(&W[kb * 128 + ch1]));
    }
    int sc_c = t & 127;
    int sn = t >> 7;
    float scale = d_stats[512 + sc_c];
    float shift = d_stats[640 + sc_c];
    float asr = __ldg(&a_src[sc_c]);
    float adr = __ldg(&a_dst[sc_c]);

    for (int i0 = blockIdx.x * 2; i0 < N_NODE; i0 += gridDim.x * 2) {
        sh[sn][sc_c] = fmaf(d_h[(i0 + sn) * HID + sc_c], scale, shift);
        __syncthreads();
        ull acc00 = 0ull, acc01 = 0ull, acc10 = 0ull, acc11 = 0ull;
        #pragma unroll
        for (int j = 0; j < 16; j++) {
            ull h0 = *(const ull*)&sh[0][k0 + 2 * j];
            ull h1 = *(const ull*)&sh[1][k0 + 2 * j];
            acc00 = ffma2(h0, w0[j], acc00);
            acc01 = ffma2(h0, w1[j], acc01);
            acc10 = ffma2(h1, w0[j], acc10);
            acc11 = ffma2(h1, w1[j], acc11);
        }
        red[0][kq * 128 + ch0] = sum2f(acc00);
        red[0][kq * 128 + ch1] = sum2f(acc01);
        red[1][kq * 128 + ch0] = sum2f(acc10);
        red[1][kq * 128 + ch1] = sum2f(acc11);
        __syncthreads();
        {
            int c = sc_c;
            float xpv = red[sn][c] + red[sn][128 + c] + red[sn][256 + c] + red[sn][384 + c];
            int ii = i0 + sn;
            d_xp[ii * HID + c] = xpv;
            float vs = xpv * asr, vd = xpv * adr;
            #pragma unroll
            for (int o = 16; o > 0; o >>= 1) {
                vs += __shfl_xor_sync(0xffffffffu, vs, o);
                vd += __shfl_xor_sync(0xffffffffu, vd, o);
            }
            if ((c & 31) == 0) {
                d_als[ii * 4 + (c >> 5)] = vs;
                d_ald[ii * 4 + (c >> 5)] = vd;
            }
        }
        __syncthreads();
    }
}

// GAT via CSR: warp per dst. Accumulates unnormalized weighted sum + denom in
// registers, normalizes at end, fuses bias+relu and BN2 stat accumulation.
// No atomics on features, no separate softmax pass, no zero-init of d_gat.
__global__ void __launch_bounds__(256) k_gat_csr(const float* __restrict__ gat_b) {
    __shared__ float s_sum[128], s_sq[128];
    int t = threadIdx.x, lane = t & 31, w = t >> 5;
    if (t < 128) { s_sum[t] = 0.f; s_sq[t] = 0.f; }
    __syncthreads();
    int c4 = lane * 4, h = lane >> 3;
    float4 bias = __ldg((const float4*)&gat_b[c4]);
    float4 lsum = {0, 0, 0, 0}, lsq = {0, 0, 0, 0};
    int warpId = blockIdx.x * 8 + w;
    int nW = gridDim.x * 8;
    for (int d = warpId; d < N_NODE; d += nW) {
        int start = d_rowptr[d], end = d_rowptr[d + 1];
        float ald_h = __ldg(&d_ald[d * 4 + h]);
        float denom = 0.f;
        float4 acc = {0, 0, 0, 0};
        for (int e = start; e < end; e++) {
            int s = __ldg(&d_ssrc[e]);
            float l = __ldg(&d_als[s * 4 + h]) + ald_h;
            l = l > 0.f ? l : 0.2f * l;
            float wt = __expf(l);
            denom += wt;
            float4 xv = __ldg((const float4*)&d_xp[s * HID + c4]);
            acc.x = fmaf(wt, xv.x, acc.x);
            acc.y = fmaf(wt, xv.y, acc.y);
            acc.z = fmaf(wt, xv.z, acc.z);
            acc.w = fmaf(wt, xv.w, acc.w);
        }
        { // self-loop
            float l = __ldg(&d_als[d * 4 + h]) + ald_h;
            l = l > 0.f ? l : 0.2f * l;
            float wt = __expf(l);
            denom += wt;
            float4 xv = __ldg((const float4*)&d_xp[d * HID + c4]);
            acc.x = fmaf(wt, xv.x, acc.x);
            acc.y = fmaf(wt, xv.y, acc.y);
            acc.z = fmaf(wt, xv.z, acc.z);
            acc.w = fmaf(wt, xv.w, acc.w);
        }
        float inv = 1.f / (denom + 1e-16f);
        float4 g;
        g.x = fmaxf(fmaf(acc.x, inv, bias.x), 0.f);
        g.y = fmaxf(fmaf(acc.y, inv, bias.y), 0.f);
        g.z = fmaxf(fmaf(acc.z, inv, bias.z), 0.f);
        g.w = fmaxf(fmaf(acc.w, inv, bias.w), 0.f);
        *(float4*)&d_gat[d * HID + c4] = g;
        lsum.x += g.x; lsum.y += g.y; lsum.z += g.z; lsum.w += g.w;
        lsq.x = fmaf(g.x, g.x, lsq.x);
        lsq.y = fmaf(g.y, g.y, lsq.y);
        lsq.z = fmaf(g.z, g.z, lsq.z);
        lsq.w = fmaf(g.w, g.w, lsq.w);
    }
    atomicAdd(&s_sum[c4 + 0], lsum.x); atomicAdd(&s_sq[c4 + 0], lsq.x);
    atomicAdd(&s_sum[c4 + 1], lsum.y); atomicAdd(&s_sq[c4 + 1], lsq.y);
    atomicAdd(&s_sum[c4 + 2], lsum.z); atomicAdd(&s_sq[c4 + 2], lsq.z);
    atomicAdd(&s_sum[c4 + 3], lsum.w); atomicAdd(&s_sq[c4 + 3], lsq.w);
    __syncthreads();
    if (t < 128) {
        atomicAdd(&d_stats[256 + t], s_sum[t]);
        atomicAdd(&d_stats[384 + t], s_sq[t]);
    }
}

// out = relu(BN2(g) @ proj_w + proj_b)
__global__ void __launch_bounds__(256) k_proj(
    const float* __restrict__ PW, const float* __restrict__ pb, float* __restrict__ out)
{
    __shared__ __align__(16) float sh[2][128];
    __shared__ float red[2][8 * 64];
    int t = threadIdx.x;
    int kq = t >> 5;
    int k0 = kq * 16;
    int cp = t & 31;
    int ch0 = cp * 2, ch1 = ch0 + 1;

    ull w0[8], w1[8];
    #pragma unroll
    for (int j = 0; j < 8; j++) {
        int ka = k0 + 2 * j, kb = ka + 1;
        w0[j] = pack2f(__ldg(&PW[ka * 64 + ch0]), __ldg(&PW[kb * 64 + ch0]));
        w1[j] = pack2f(__ldg(&PW[ka * 64 + ch1]), __ldg(&PW[kb * 64 + ch1]));
    }
    int sc_c = t & 127;
    int sn = t >> 7;
    float scale = d_stats[768 + sc_c];
    float shift = d_stats[896 + sc_c];

    for (int i0 = blockIdx.x * 2; i0 < N_NODE; i0 += gridDim.x * 2) {
        sh[sn][sc_c] = fmaf(d_gat[(i0 + sn) * HID + sc_c], scale, shift);
        __syncthreads();
        ull acc00 = 0ull, acc01 = 0ull, acc10 = 0ull, acc11 = 0ull;
        #pragma unroll
        for (int j = 0; j < 8; j++) {
            ull h0 = *(const ull*)&sh[0][k0 + 2 * j];
            ull h1 = *(const ull*)&sh[1][k0 + 2 * j];
            acc00 = ffma2(h0, w0[j], acc00);
            acc01 = ffma2(h0, w1[j], acc01);
            acc10 = ffma2(h1, w0[j], acc10);
            acc11 = ffma2(h1, w1[j], acc11);
        }
        red[0][kq * 64 + ch0] = sum2f(acc00);
        red[0][kq * 64 + ch1] = sum2f(acc01);
        red[1][kq * 64 + ch0] = sum2f(acc10);
        red[1][kq * 64 + ch1] = sum2f(acc11);
        __syncthreads();
        if (t < 128) {
            int n = t >> 6, o = t & 63;
            float v = 0.f;
            #pragma unroll
            for (int q = 0; q < 8; q++) v += red[n][q * 64 + o];
            v += __ldg(&pb[o]);
            out[(i0 + n) * OUTD + o] = fmaxf(v, 0.f);
        }
        __syncthreads();
    }
}

// ---------------- launch ----------------
extern "C" void kernel_launch(void* const* d_in, const int* in_sizes, int n_in,
                              void* d_out, int out_size) {
    const float* x_user   = (const float*)d_in[0];
    const float* x_wallet = (const float*)d_in[1];
    const float* w_w2u_l = (const float*)d_in[5];
    const float* b_w2u   = (const float*)d_in[6];
    const float* w_w2u_r = (const float*)d_in[7];
    const float* w_u2u_l = (const float*)d_in[8];
    const float* b_u2u   = (const float*)d_in[9];
    const float* w_u2u_r = (const float*)d_in[10];
    const float* bn_u_g  = (const float*)d_in[11];
    const float* bn_u_b  = (const float*)d_in[12];
    const float* gat_w  = (const float*)d_in[15];
    const float* gat_as = (const float*)d_in[16];
    const float* gat_ad = (const float*)d_in[17];
    const float* gat_b  = (const float*)d_in[18];
    const float* bn2_g  = (const float*)d_in[19];
    const float* bn2_b  = (const float*)d_in[20];
    const float* proj_w = (const float*)d_in[21];
    const float* proj_b = (const float*)d_in[22];
    const int* ei_wu = (const int*)d_in[24];
    const int* ei_uu = (const int*)d_in[25];
    float* out = (float*)d_out;

    k_zero<<<512, 256>>>();
    k_hist<<<2048, 256>>>(ei_uu);
    k_edge_wu<<<2048, 256>>>(x_wallet, ei_wu);
    k_scan1<<<98, 256>>>();
    k_scan2<<<1, 128>>>();
    k_scan3<<<98, 256>>>();
    k_scatter<<<2048, 256>>>(ei_uu);
    k_agg_uu<<<1024, 256>>>(x_user);
    k_sage_node<<<1184, 128>>>(x_user, w_w2u_l, b_w2u, w_w2u_r, w_u2u_l, b_u2u, w_u2u_r);
    k_bn_fin<<<1, 128>>>(bn_u_g, bn_u_b, 0, 512);
    k_xp<<<1024, 256>>>(gat_w, gat_as, gat_ad);
    k_gat_csr<<<1024, 256>>>(gat_b);
    k_bn_fin<<<1, 128>>>(bn2_g, bn2_b, 256, 768);
    k_proj<<<1024, 256>>>(proj_w, proj_b, out);
}